// round 1
// baseline (speedup 1.0000x reference)
#include <cuda_runtime.h>
#include <math.h>

#define CH 256
#define NBATCH 64
#define HW 1024
#define MTOT 65536   // NBATCH * HW
#define EPSV 1e-5f
#define T_ITERS 10

// ---------------- device scratch (static: no allocations allowed) ----------------
__device__ float g_mean[CH];
__device__ float g_scal[2];            // [0] = 1/trace, [1] = sqrt(1/trace)
__device__ float g_bias[CH];
__device__ float g_Sig [CH*CH];
__device__ float g_SigN[CH*CH];
__device__ float g_P   [CH*CH];
__device__ float g_T1  [CH*CH];
__device__ float g_T2  [CH*CH];
__device__ float g_M   [CH*CH];
__device__ float g_part[384*16384];    // 3 tiles x 128 (n,p)-splits x 128x128 partials

// ---------------- packed fp32x2 FMA (FFMA2): 2x fp32 throughput on sm_103a ----------------
__device__ __forceinline__ float2 f2fma(float2 a, float2 b, float2 c) {
    union U { float2 f; unsigned long long u; };
    U ua, ub, uc, ud;
    ua.f = a; ub.f = b; uc.f = c;
    asm("fma.rn.f32x2 %0, %1, %2, %3;" : "=l"(ud.u) : "l"(ua.u), "l"(ub.u), "l"(uc.u));
    return ud.f;
}

// ---------------- per-channel mean ----------------
__global__ void k_mean(const float* __restrict__ X) {
    int c = blockIdx.x, t = threadIdx.x;
    const float* xc = X + (size_t)c * HW;
    float s = 0.f;
    for (int j = t; j < MTOT; j += 256) {
        int n = j >> 10, p = j & 1023;
        s += xc[(size_t)n * (CH*HW) + p];
    }
    __shared__ float sm[256];
    sm[t] = s; __syncthreads();
    for (int o = 128; o > 0; o >>= 1) { if (t < o) sm[t] += sm[t+o]; __syncthreads(); }
    if (t == 0) g_mean[c] = sm[0] * (1.f / (float)MTOT);
}

// ---------------- Gram partials: raw X X^T over a (n, p-half) chunk ----------------
// tile 0: rows [0,128) x cols [0,128); tile 1: [0,128)x[128,256); tile 2: [128,256)x[128,256)
__global__ void __launch_bounds__(256) k_gram(const float* __restrict__ X) {
    int tile = blockIdx.x;
    int ci0 = (tile == 2) ? 128 : 0;
    int cj0 = (tile >= 1) ? 128 : 0;
    int n   = blockIdx.y >> 1;
    int pb0 = (blockIdx.y & 1) * 512;
    const float* Xn = X + (size_t)n * (CH*HW);

    __shared__ float As[128][17];   // As[i][k]  (row i = channel ci0+i, k = p offset)
    __shared__ float Bs[16][132];   // Bs[k][j]  (j = channel cj0+j)

    int tid = threadIdx.x;
    int tx = tid & 15, ty = tid >> 4;

    float2 acc[8][4];
    #pragma unroll
    for (int m = 0; m < 8; m++)
        #pragma unroll
        for (int j = 0; j < 4; j++) acc[m][j] = make_float2(0.f, 0.f);

    for (int pb = pb0; pb < pb0 + 512; pb += 16) {
        #pragma unroll
        for (int l = 0; l < 2; l++) {
            int q = tid + l*256;
            int row = q >> 2, fc = q & 3;
            float4 v = *reinterpret_cast<const float4*>(Xn + (size_t)(ci0+row)*HW + pb + fc*4);
            As[row][fc*4+0] = v.x; As[row][fc*4+1] = v.y;
            As[row][fc*4+2] = v.z; As[row][fc*4+3] = v.w;
            float4 w = *reinterpret_cast<const float4*>(Xn + (size_t)(cj0+row)*HW + pb + fc*4);
            Bs[fc*4+0][row] = w.x; Bs[fc*4+1][row] = w.y;
            Bs[fc*4+2][row] = w.z; Bs[fc*4+3][row] = w.w;
        }
        __syncthreads();
        #pragma unroll
        for (int k = 0; k < 16; k++) {
            float2 a2[8], b2[4];
            #pragma unroll
            for (int m = 0; m < 8; m++) { float a = As[ty*8+m][k]; a2[m] = make_float2(a, a); }
            float4 u0 = *reinterpret_cast<float4*>(&Bs[k][tx*8]);
            float4 u1 = *reinterpret_cast<float4*>(&Bs[k][tx*8+4]);
            b2[0] = make_float2(u0.x,u0.y); b2[1] = make_float2(u0.z,u0.w);
            b2[2] = make_float2(u1.x,u1.y); b2[3] = make_float2(u1.z,u1.w);
            #pragma unroll
            for (int m = 0; m < 8; m++)
                #pragma unroll
                for (int j = 0; j < 4; j++)
                    acc[m][j] = f2fma(a2[m], b2[j], acc[m][j]);
        }
        __syncthreads();
    }
    float* pp = g_part + ((size_t)tile*128 + blockIdx.y) * 16384;
    #pragma unroll
    for (int m = 0; m < 8; m++) {
        int i = ty*8 + m;
        float4 o0 = make_float4(acc[m][0].x, acc[m][0].y, acc[m][1].x, acc[m][1].y);
        float4 o1 = make_float4(acc[m][2].x, acc[m][2].y, acc[m][3].x, acc[m][3].y);
        *reinterpret_cast<float4*>(pp + i*128 + tx*8)     = o0;
        *reinterpret_cast<float4*>(pp + i*128 + tx*8 + 4) = o1;
    }
}

// ---------------- reduce partials, finalize Sigma = eps*I + raw/m - mean mean^T ----------------
__global__ void k_sigfin() {
    int idx = blockIdx.x*256 + threadIdx.x;
    int c = idx >> 8, d = idx & 255;
    int t, i, j;
    if (c < 128) { if (d < 128) { t=0; i=c; j=d; } else { t=1; i=c; j=d-128; } }
    else         { if (d < 128) { t=1; i=d; j=c-128; } else { t=2; i=c-128; j=d-128; } }
    const float* pp = g_part + (size_t)t*128*16384 + i*128 + j;
    float s = 0.f;
    #pragma unroll 8
    for (int q = 0; q < 128; q++) s += pp[(size_t)q*16384];
    float v = s * (1.f / (float)MTOT) - g_mean[c]*g_mean[d];
    if (c == d) v += EPSV;
    g_Sig[idx] = v;
}

__global__ void k_trace() {
    int t = threadIdx.x;
    __shared__ float sm[256];
    sm[t] = g_Sig[t*257];
    __syncthreads();
    for (int o = 128; o > 0; o >>= 1) { if (t < o) sm[t] += sm[t+o]; __syncthreads(); }
    if (t == 0) { float tr = sm[0]; g_scal[0] = 1.f/tr; g_scal[1] = sqrtf(1.f/tr); }
}

__global__ void k_init() {
    int idx = blockIdx.x*256 + threadIdx.x;
    g_SigN[idx] = g_Sig[idx] * g_scal[0];
    g_P[idx] = ((idx >> 8) == (idx & 255)) ? 1.f : 0.f;
}

// ---------------- generic 256x256x256 matmul ----------------
// mode 0: C = A*B     mode 1: C = 1.5*C_old - 0.5*A*B     mode 2: C = scal[1]*(A*B)
__global__ void __launch_bounds__(256) k_mm(float* __restrict__ Cm,
                                            const float* __restrict__ A,
                                            const float* __restrict__ B, int mode) {
    __shared__ float As[32][33];
    __shared__ float Bs[32][36];
    int tid = threadIdx.x;
    int tx = tid & 15, ty = tid >> 4;
    int r0 = blockIdx.y*32, c0 = blockIdx.x*32;
    float2 acc0 = make_float2(0.f,0.f), acc1 = make_float2(0.f,0.f);
    for (int kb = 0; kb < 256; kb += 32) {
        int row = tid >> 3, fc = tid & 7;
        float4 v = *reinterpret_cast<const float4*>(A + (r0+row)*256 + kb + fc*4);
        As[row][fc*4+0]=v.x; As[row][fc*4+1]=v.y; As[row][fc*4+2]=v.z; As[row][fc*4+3]=v.w;
        float4 w = *reinterpret_cast<const float4*>(B + (kb+row)*256 + c0 + fc*4);
        *reinterpret_cast<float4*>(&Bs[row][fc*4]) = w;
        __syncthreads();
        #pragma unroll
        for (int k = 0; k < 32; k++) {
            float a0 = As[ty*2][k], a1 = As[ty*2+1][k];
            float2 b = *reinterpret_cast<float2*>(&Bs[k][tx*2]);
            acc0 = f2fma(make_float2(a0,a0), b, acc0);
            acc1 = f2fma(make_float2(a1,a1), b, acc1);
        }
        __syncthreads();
    }
    int r = r0 + ty*2, cc = c0 + tx*2;
    float2* o0 = reinterpret_cast<float2*>(Cm + r*256 + cc);
    float2* o1 = reinterpret_cast<float2*>(Cm + (r+1)*256 + cc);
    if (mode == 0) { *o0 = acc0; *o1 = acc1; }
    else if (mode == 1) {
        float2 d0 = *o0, d1 = *o1;
        *o0 = make_float2(1.5f*d0.x - 0.5f*acc0.x, 1.5f*d0.y - 0.5f*acc0.y);
        *o1 = make_float2(1.5f*d1.x - 0.5f*acc1.x, 1.5f*d1.y - 0.5f*acc1.y);
    } else {
        float s = g_scal[1];
        *o0 = make_float2(s*acc0.x, s*acc0.y);
        *o1 = make_float2(s*acc1.x, s*acc1.y);
    }
}

__global__ void k_bias() {
    int d = threadIdx.x;
    float s = 0.f;
    for (int c2 = 0; c2 < 256; c2++) s += g_M[d*256 + c2] * g_mean[c2];
    g_bias[d] = s;
}

// ---------------- final: out[n,d,p] = sum_c M[d,c] X[n,c,p] - bias[d] ----------------
__global__ void __launch_bounds__(256) k_out(const float* __restrict__ X, float* __restrict__ out) {
    int d0 = blockIdx.x * 128, p0 = blockIdx.y * 128;
    const float* Xn = X   + (size_t)blockIdx.z * (CH*HW);
    float*       On = out + (size_t)blockIdx.z * (CH*HW);
    __shared__ float Ms[128][17];   // Ms[i][k] = M[d0+i][kb+k]
    __shared__ float Xs[16][132];   // Xs[k][j] = X[n][kb+k][p0+j]
    int tid = threadIdx.x, tx = tid & 15, ty = tid >> 4;
    float2 acc[8][4];
    #pragma unroll
    for (int m = 0; m < 8; m++)
        #pragma unroll
        for (int j = 0; j < 4; j++) acc[m][j] = make_float2(0.f, 0.f);

    for (int kb = 0; kb < 256; kb += 16) {
        #pragma unroll
        for (int l = 0; l < 2; l++) {
            int q = tid + l*256;
            int row = q >> 2, fc = q & 3;
            float4 v = *reinterpret_cast<const float4*>(g_M + (d0+row)*256 + kb + fc*4);
            Ms[row][fc*4+0]=v.x; Ms[row][fc*4+1]=v.y; Ms[row][fc*4+2]=v.z; Ms[row][fc*4+3]=v.w;
            int k = q >> 5, fcx = q & 31;
            float4 w = *reinterpret_cast<const float4*>(Xn + (size_t)(kb+k)*HW + p0 + fcx*4);
            *reinterpret_cast<float4*>(&Xs[k][fcx*4]) = w;
        }
        __syncthreads();
        #pragma unroll
        for (int k = 0; k < 16; k++) {
            float2 a2[8], b2[4];
            #pragma unroll
            for (int m = 0; m < 8; m++) { float a = Ms[ty*8+m][k]; a2[m] = make_float2(a, a); }
            float4 u0 = *reinterpret_cast<float4*>(&Xs[k][tx*8]);
            float4 u1 = *reinterpret_cast<float4*>(&Xs[k][tx*8+4]);
            b2[0] = make_float2(u0.x,u0.y); b2[1] = make_float2(u0.z,u0.w);
            b2[2] = make_float2(u1.x,u1.y); b2[3] = make_float2(u1.z,u1.w);
            #pragma unroll
            for (int m = 0; m < 8; m++)
                #pragma unroll
                for (int j = 0; j < 4; j++)
                    acc[m][j] = f2fma(a2[m], b2[j], acc[m][j]);
        }
        __syncthreads();
    }
    #pragma unroll
    for (int m = 0; m < 8; m++) {
        int i = ty*8 + m;
        float b = g_bias[d0 + i];
        float4 o0 = make_float4(acc[m][0].x - b, acc[m][0].y - b, acc[m][1].x - b, acc[m][1].y - b);
        float4 o1 = make_float4(acc[m][2].x - b, acc[m][2].y - b, acc[m][3].x - b, acc[m][3].y - b);
        *reinterpret_cast<float4*>(On + (size_t)(d0+i)*HW + p0 + tx*8)     = o0;
        *reinterpret_cast<float4*>(On + (size_t)(d0+i)*HW + p0 + tx*8 + 4) = o1;
    }
}

// ---------------- launch ----------------
extern "C" void kernel_launch(void* const* d_in, const int* in_sizes, int n_in,
                              void* d_out, int out_size) {
    const float* X   = (const float*)d_in[0];
    const float* rot = (const float*)d_in[1];
    if (n_in >= 2 && in_sizes[0] == CH*CH && in_sizes[1] != CH*CH) {  // defensive order check
        X = (const float*)d_in[1]; rot = (const float*)d_in[0];
    }
    float* out = (float*)d_out;
    (void)out_size;

    float *P, *T1, *T2, *SigN, *M;
    cudaGetSymbolAddress((void**)&P,    g_P);
    cudaGetSymbolAddress((void**)&T1,   g_T1);
    cudaGetSymbolAddress((void**)&T2,   g_T2);
    cudaGetSymbolAddress((void**)&SigN, g_SigN);
    cudaGetSymbolAddress((void**)&M,    g_M);

    k_mean<<<256, 256>>>(X);
    k_gram<<<dim3(3,128), 256>>>(X);
    k_sigfin<<<256, 256>>>();
    k_trace<<<1, 256>>>();
    k_init<<<256, 256>>>();
    for (int it = 0; it < T_ITERS; it++) {
        k_mm<<<dim3(8,8), 256>>>(T1, P,  P,    0);   // T1 = P*P
        k_mm<<<dim3(8,8), 256>>>(T2, T1, P,    0);   // T2 = (P*P)*P
        k_mm<<<dim3(8,8), 256>>>(P,  T2, SigN, 1);   // P  = 1.5P - 0.5*T2*SigN
    }
    k_mm<<<dim3(8,8), 256>>>(M, rot, P, 2);          // M = sqrt(1/tr) * rot * P
    k_bias<<<1, 256>>>();
    k_out<<<dim3(2,8,64), 256>>>(X, out);
}

// round 3
// speedup vs baseline: 1.7118x; 1.7118x over previous
#include <cuda_runtime.h>
#include <cuda_bf16.h>
#include <math.h>
#include <stdint.h>

#define CH 256
#define NBATCH 64
#define HW 1024
#define MTOT 65536
#define EPSV 1e-5f
#define T_ITERS 10

// ---------------- device scratch (no allocations allowed) ----------------
__device__ float g_mean[CH];
__device__ float g_msum[CH*NBATCH];
__device__ float g_scal[2];
__device__ float g_bias[CH];
__device__ float g_Sig [CH*CH];
__device__ float g_SigN[CH*CH];
__device__ float g_P   [CH*CH];
__device__ float g_T1  [CH*CH];
__device__ float g_T2  [CH*CH];
__device__ float g_M   [CH*CH];
__device__ float g_part[192*16384];            // 3 quadrants x 64 splits x 128x128
__device__ __nv_bfloat16 g_xhi[64L*256*1024];  // [n][c][p]
__device__ __nv_bfloat16 g_xlo[64L*256*1024];
__device__ __nv_bfloat16 g_Mhi[CH*CH];
__device__ __nv_bfloat16 g_Mlo[CH*CH];

// ---------------- helpers ----------------
__device__ __forceinline__ uint32_t smem_u32(const void* p) {
    uint32_t a;
    asm("{ .reg .u64 t; cvta.to.shared.u64 t, %1; cvt.u32.u64 %0, t; }" : "=r"(a) : "l"(p));
    return a;
}
__device__ __forceinline__ float2 f2fma(float2 a, float2 b, float2 c) {
    union U { float2 f; unsigned long long u; };
    U ua, ub, uc, ud;
    ua.f = a; ub.f = b; uc.f = c;
    asm("fma.rn.f32x2 %0, %1, %2, %3;" : "=l"(ud.u) : "l"(ua.u), "l"(ub.u), "l"(uc.u));
    return ud.f;
}
__device__ __forceinline__ void ldm_x4(uint32_t* r, uint32_t addr) {
    asm volatile("ldmatrix.sync.aligned.m8n8.x4.shared.b16 {%0,%1,%2,%3}, [%4];"
        : "=r"(r[0]), "=r"(r[1]), "=r"(r[2]), "=r"(r[3]) : "r"(addr));
}
__device__ __forceinline__ void ldm_x2(uint32_t* r, uint32_t addr) {
    asm volatile("ldmatrix.sync.aligned.m8n8.x2.shared.b16 {%0,%1}, [%2];"
        : "=r"(r[0]), "=r"(r[1]) : "r"(addr));
}
__device__ __forceinline__ void ldm_x2t(uint32_t* r, uint32_t addr) {
    asm volatile("ldmatrix.sync.aligned.m8n8.x2.trans.shared.b16 {%0,%1}, [%2];"
        : "=r"(r[0]), "=r"(r[1]) : "r"(addr));
}
__device__ __forceinline__ void mma_bf16(float* c, const uint32_t* a, const uint32_t* b) {
    asm volatile("mma.sync.aligned.m16n8k16.row.col.f32.bf16.bf16.f32 "
        "{%0,%1,%2,%3}, {%4,%5,%6,%7}, {%8,%9}, {%0,%1,%2,%3};"
        : "+f"(c[0]), "+f"(c[1]), "+f"(c[2]), "+f"(c[3])
        : "r"(a[0]), "r"(a[1]), "r"(a[2]), "r"(a[3]), "r"(b[0]), "r"(b[1]));
}

// ---------------- convert X -> bf16 hi/lo + per-(c,n) sums ----------------
__global__ void __launch_bounds__(256) k_conv1(const float* __restrict__ X) {
    int c = blockIdx.x, n = blockIdx.y, t = threadIdx.x;
    size_t base = ((size_t)n*CH + c) * HW;
    float4 v = *(const float4*)(X + base + t*4);
    float f[4] = {v.x, v.y, v.z, v.w};
    __nv_bfloat16 h[4], l[4];
    #pragma unroll
    for (int k = 0; k < 4; k++) {
        h[k] = __float2bfloat16(f[k]);
        l[k] = __float2bfloat16(f[k] - __bfloat162float(h[k]));
    }
    __nv_bfloat162* ph = (__nv_bfloat162*)(g_xhi + base);
    __nv_bfloat162* pl = (__nv_bfloat162*)(g_xlo + base);
    ph[t*2]   = __nv_bfloat162(h[0], h[1]);
    ph[t*2+1] = __nv_bfloat162(h[2], h[3]);
    pl[t*2]   = __nv_bfloat162(l[0], l[1]);
    pl[t*2+1] = __nv_bfloat162(l[2], l[3]);
    float s = f[0] + f[1] + f[2] + f[3];
    __shared__ float sm[256];
    sm[t] = s; __syncthreads();
    for (int o = 128; o > 0; o >>= 1) { if (t < o) sm[t] += sm[t+o]; __syncthreads(); }
    if (t == 0) g_msum[c*NBATCH + n] = sm[0];
}

__global__ void k_meanred() {
    int c = threadIdx.x;
    float s = 0.f;
    for (int n = 0; n < NBATCH; n++) s += g_msum[c*NBATCH + n];
    g_mean[c] = s * (1.f / (float)MTOT);
}

// ---------------- Gram via mma.sync: quadrants (0,0),(0,1),(1,1) x 64 n-splits ----------------
// smem: sAh[128][72], sAl, sBh, sBl  (72 = 64 + 8 pad halves)
#define GRAM_SMEM (4*128*72*2)
__global__ void __launch_bounds__(256, 1) k_gram_mma() {
    extern __shared__ char sm[];
    __nv_bfloat16* sAh = (__nv_bfloat16*)sm;
    int q = blockIdx.x, n = blockIdx.y;
    int ci0 = (q == 2) ? 128 : 0;
    int cj0 = (q == 0) ? 0 : 128;
    int tid = threadIdx.x, lane = tid & 31, wid = tid >> 5;
    int wm = wid >> 2, wn = wid & 3;
    uint32_t sbase = smem_u32(sm);
    const uint32_t TILE = 128*72*2;   // bytes per tile

    float acc[4][4][4];
    #pragma unroll
    for (int a = 0; a < 4; a++)
        #pragma unroll
        for (int b = 0; b < 4; b++)
            #pragma unroll
            for (int k = 0; k < 4; k++) acc[a][b][k] = 0.f;

    for (int pb = 0; pb < 1024; pb += 64) {
        __syncthreads();
        #pragma unroll
        for (int l = 0; l < 4; l++) {
            int i = tid + l*256;
            int row = i >> 3, fc = i & 7;
            size_t gA = ((size_t)n*CH + ci0 + row)*HW + pb + fc*8;
            size_t gB = ((size_t)n*CH + cj0 + row)*HW + pb + fc*8;
            int so = row*72 + fc*8;
            *(float4*)(sAh + so)               = *(const float4*)(g_xhi + gA);
            *(float4*)(sAh + 128*72 + so)      = *(const float4*)(g_xlo + gA);
            *(float4*)(sAh + 2*128*72 + so)    = *(const float4*)(g_xhi + gB);
            *(float4*)(sAh + 3*128*72 + so)    = *(const float4*)(g_xlo + gB);
        }
        __syncthreads();
        #pragma unroll
        for (int ks = 0; ks < 4; ks++) {
            int k0 = ks*16;
            uint32_t ah[4][4], al[4][4], bh[4][2], bl[4][2];
            int ar = lane & 15, ac = (lane >> 4) * 8;
            #pragma unroll
            for (int mt = 0; mt < 4; mt++) {
                uint32_t ao = sbase + ((wm*64 + mt*16 + ar)*72 + k0 + ac)*2;
                ldm_x4(ah[mt], ao);
                ldm_x4(al[mt], ao + TILE);
            }
            int br = lane & 7, bc = ((lane >> 3) & 1) * 8;
            #pragma unroll
            for (int nt = 0; nt < 4; nt++) {
                uint32_t bo = sbase + 2*TILE + ((wn*32 + nt*8 + br)*72 + k0 + bc)*2;
                ldm_x2(bh[nt], bo);
                ldm_x2(bl[nt], bo + TILE);
            }
            #pragma unroll
            for (int mt = 0; mt < 4; mt++)
                #pragma unroll
                for (int nt = 0; nt < 4; nt++) {
                    mma_bf16(acc[mt][nt], ah[mt], bh[nt]);
                    mma_bf16(acc[mt][nt], ah[mt], bl[nt]);
                    mma_bf16(acc[mt][nt], al[mt], bh[nt]);
                }
        }
    }
    float* pout = g_part + ((size_t)q*64 + n)*16384;
    int rg = lane >> 2, cg = (lane & 3)*2;
    #pragma unroll
    for (int mt = 0; mt < 4; mt++)
        #pragma unroll
        for (int nt = 0; nt < 4; nt++) {
            int r0 = wm*64 + mt*16 + rg, c0 = wn*32 + nt*8 + cg;
            *(float2*)(pout + r0*128 + c0)     = make_float2(acc[mt][nt][0], acc[mt][nt][1]);
            *(float2*)(pout + (r0+8)*128 + c0) = make_float2(acc[mt][nt][2], acc[mt][nt][3]);
        }
}

// ---------------- finalize Sigma ----------------
__global__ void k_sigfin() {
    int idx = blockIdx.x*256 + threadIdx.x;
    int a = idx >> 8, b = idx & 255;
    int q, i, j;
    if (a < 128) { if (b < 128) { q=0; i=a; j=b; } else { q=1; i=a; j=b-128; } }
    else         { if (b < 128) { q=1; i=b; j=a-128; } else { q=2; i=a-128; j=b-128; } }
    const float* pp = g_part + (size_t)q*64*16384 + i*128 + j;
    float s = 0.f;
    #pragma unroll 8
    for (int t = 0; t < 64; t++) s += pp[(size_t)t*16384];
    float v = s * (1.f / (float)MTOT) - g_mean[a]*g_mean[b];
    if (a == b) v += EPSV;
    g_Sig[idx] = v;
}

__global__ void k_trace() {
    int t = threadIdx.x;
    __shared__ float sm[256];
    sm[t] = g_Sig[t*257];
    __syncthreads();
    for (int o = 128; o > 0; o >>= 1) { if (t < o) sm[t] += sm[t+o]; __syncthreads(); }
    if (t == 0) { float tr = sm[0]; g_scal[0] = 1.f/tr; g_scal[1] = sqrtf(1.f/tr); }
}

__global__ void k_init() {
    int idx = blockIdx.x*256 + threadIdx.x;
    g_SigN[idx] = g_Sig[idx] * g_scal[0];
    g_P[idx] = ((idx >> 8) == (idx & 255)) ? 1.f : 0.f;
}

// ---------------- 256^3 fp32 matmul (FFMA2) for Newton ----------------
// mode 0: C = A*B   mode 1: C = 1.5*C - 0.5*A*B   mode 2: C = scal[1]*A*B (+ bf16 split)
__device__ __forceinline__ void mm_core(float* __restrict__ Cm,
                                        const float* __restrict__ A,
                                        const float* __restrict__ B, int mode) {
    __shared__ float As[32][33];
    __shared__ float Bs[32][36];
    int tid = threadIdx.x;
    int tx = tid & 15, ty = tid >> 4;
    int r0 = blockIdx.y*32, c0 = blockIdx.x*32;
    float2 acc0 = make_float2(0.f,0.f), acc1 = make_float2(0.f,0.f);
    for (int kb = 0; kb < 256; kb += 32) {
        int row = tid >> 3, fc = tid & 7;
        float4 v = *(const float4*)(A + (r0+row)*256 + kb + fc*4);
        As[row][fc*4+0]=v.x; As[row][fc*4+1]=v.y; As[row][fc*4+2]=v.z; As[row][fc*4+3]=v.w;
        float4 w = *(const float4*)(B + (kb+row)*256 + c0 + fc*4);
        *(float4*)(&Bs[row][fc*4]) = w;
        __syncthreads();
        #pragma unroll
        for (int k = 0; k < 32; k++) {
            float a0 = As[ty*2][k], a1 = As[ty*2+1][k];
            float2 b = *(float2*)(&Bs[k][tx*2]);
            acc0 = f2fma(make_float2(a0,a0), b, acc0);
            acc1 = f2fma(make_float2(a1,a1), b, acc1);
        }
        __syncthreads();
    }
    int r = r0 + ty*2, cc = c0 + tx*2;
    float2* o0 = (float2*)(Cm + r*256 + cc);
    float2* o1 = (float2*)(Cm + (r+1)*256 + cc);
    if (mode == 0) { *o0 = acc0; *o1 = acc1; }
    else if (mode == 1) {
        float2 d0 = *o0, d1 = *o1;
        *o0 = make_float2(1.5f*d0.x - 0.5f*acc0.x, 1.5f*d0.y - 0.5f*acc0.y);
        *o1 = make_float2(1.5f*d1.x - 0.5f*acc1.x, 1.5f*d1.y - 0.5f*acc1.y);
    } else {
        float s = g_scal[1];
        float2 v0 = make_float2(s*acc0.x, s*acc0.y);
        float2 v1 = make_float2(s*acc1.x, s*acc1.y);
        *o0 = v0; *o1 = v1;
        float f[4] = {v0.x, v0.y, v1.x, v1.y};
        int  off[4] = {r*256+cc, r*256+cc+1, (r+1)*256+cc, (r+1)*256+cc+1};
        #pragma unroll
        for (int k = 0; k < 4; k++) {
            __nv_bfloat16 h = __float2bfloat16(f[k]);
            g_Mhi[off[k]] = h;
            g_Mlo[off[k]] = __float2bfloat16(f[k] - __bfloat162float(h));
        }
    }
}
__global__ void __launch_bounds__(256) k_mm(float* Cm, const float* A, const float* B, int mode) {
    mm_core(Cm, A, B, mode);
}
__global__ void __launch_bounds__(256) k_mm2() {
    if (blockIdx.z == 0) mm_core(g_T1, g_P, g_P, 0);
    else                 mm_core(g_T2, g_P, g_SigN, 0);
}

__global__ void k_bias() {
    int d = threadIdx.x;
    float s = 0.f;
    for (int c2 = 0; c2 < 256; c2++) s += g_M[d*256 + c2] * g_mean[c2];
    g_bias[d] = s;
}

// ---------------- output GEMM: out[n][d][p] = sum_c M[d][c] X[n][c][p] - bias[d] ----------------
// A = M hi/lo [128 d][72], B = X hi/lo [64 c][136 p] (trans ldmatrix)
#define OUT_SMEM (2*128*72*2 + 2*64*136*2)
__global__ void __launch_bounds__(256, 1) k_out_mma(float* __restrict__ out) {
    extern __shared__ char sm[];
    __nv_bfloat16* sA = (__nv_bfloat16*)sm;            // [hi|lo][128][72]
    __nv_bfloat16* sB = sA + 2*128*72;                  // [hi|lo][64][136]
    int p0 = blockIdx.x*128, d0 = blockIdx.y*128, n = blockIdx.z;
    int tid = threadIdx.x, lane = tid & 31, wid = tid >> 5;
    int wm = wid >> 2, wn = wid & 3;
    uint32_t sbase = smem_u32(sm);
    const uint32_t ATILE = 128*72*2, BBASE = 2*ATILE, BTILE = 64*136*2;

    float acc[4][4][4];
    #pragma unroll
    for (int a = 0; a < 4; a++)
        #pragma unroll
        for (int b = 0; b < 4; b++)
            #pragma unroll
            for (int k = 0; k < 4; k++) acc[a][b][k] = 0.f;

    for (int cb = 0; cb < 256; cb += 64) {
        __syncthreads();
        #pragma unroll
        for (int l = 0; l < 4; l++) {
            int i = tid + l*256;
            // A: 128 rows x 8 float4
            int rowA = i >> 3, fa = i & 7;
            int gM = (d0 + rowA)*256 + cb + fa*8;
            int soA = rowA*72 + fa*8;
            *(float4*)(sA + soA)          = *(const float4*)(g_Mhi + gM);
            *(float4*)(sA + 128*72 + soA) = *(const float4*)(g_Mlo + gM);
            // B: 64 rows x 16 float4
            int rowB = i >> 4, fb = i & 15;
            size_t gX = ((size_t)n*CH + cb + rowB)*HW + p0 + fb*8;
            int soB = rowB*136 + fb*8;
            *(float4*)(sB + soB)          = *(const float4*)(g_xhi + gX);
            *(float4*)(sB + 64*136 + soB) = *(const float4*)(g_xlo + gX);
        }
        __syncthreads();
        #pragma unroll
        for (int ks = 0; ks < 4; ks++) {
            int k0 = ks*16;
            uint32_t ah[4][4], al[4][4], bh[4][2], bl[4][2];
            int ar = lane & 15, ac = (lane >> 4) * 8;
            #pragma unroll
            for (int mt = 0; mt < 4; mt++) {
                uint32_t ao = sbase + ((wm*64 + mt*16 + ar)*72 + k0 + ac)*2;
                ldm_x4(ah[mt], ao);
                ldm_x4(al[mt], ao + ATILE);
            }
            int br = lane & 15;
            #pragma unroll
            for (int nt = 0; nt < 4; nt++) {
                uint32_t bo = sbase + BBASE + ((k0 + br)*136 + wn*32 + nt*8)*2;
                ldm_x2t(bh[nt], bo);
                ldm_x2t(bl[nt], bo + BTILE);
            }
            #pragma unroll
            for (int mt = 0; mt < 4; mt++)
                #pragma unroll
                for (int nt = 0; nt < 4; nt++) {
                    mma_bf16(acc[mt][nt], ah[mt], bh[nt]);
                    mma_bf16(acc[mt][nt], ah[mt], bl[nt]);
                    mma_bf16(acc[mt][nt], al[mt], bh[nt]);
                }
        }
    }
    float* On = out + (size_t)n * (CH*HW);
    int rg = lane >> 2, cg = (lane & 3)*2;
    #pragma unroll
    for (int mt = 0; mt < 4; mt++) {
        int d = d0 + wm*64 + mt*16 + rg;
        float b0 = g_bias[d], b1 = g_bias[d+8];
        #pragma unroll
        for (int nt = 0; nt < 4; nt++) {
            int p = p0 + wn*32 + nt*8 + cg;
            *(float2*)(On + (size_t)d*HW + p)     = make_float2(acc[mt][nt][0]-b0, acc[mt][nt][1]-b0);
            *(float2*)(On + (size_t)(d+8)*HW + p) = make_float2(acc[mt][nt][2]-b1, acc[mt][nt][3]-b1);
        }
    }
}

// ---------------- launch ----------------
extern "C" void kernel_launch(void* const* d_in, const int* in_sizes, int n_in,
                              void* d_out, int out_size) {
    const float* X   = (const float*)d_in[0];
    const float* rot = (const float*)d_in[1];
    if (n_in >= 2 && in_sizes[0] == CH*CH && in_sizes[1] != CH*CH) {
        X = (const float*)d_in[1]; rot = (const float*)d_in[0];
    }
    float* out = (float*)d_out;
    (void)out_size;

    float *P, *T1, *T2, *M;
    cudaGetSymbolAddress((void**)&P,  g_P);
    cudaGetSymbolAddress((void**)&T1, g_T1);
    cudaGetSymbolAddress((void**)&T2, g_T2);
    cudaGetSymbolAddress((void**)&M,  g_M);

    cudaFuncSetAttribute(k_gram_mma, cudaFuncAttributeMaxDynamicSharedMemorySize, GRAM_SMEM);
    cudaFuncSetAttribute(k_out_mma,  cudaFuncAttributeMaxDynamicSharedMemorySize, OUT_SMEM);

    k_conv1<<<dim3(256, 64), 256>>>(X);
    k_meanred<<<1, 256>>>();
    k_gram_mma<<<dim3(3, 64), 256, GRAM_SMEM>>>();
    k_sigfin<<<256, 256>>>();
    k_trace<<<1, 256>>>();
    k_init<<<256, 256>>>();
    for (int it = 0; it < T_ITERS; it++) {
        k_mm2<<<dim3(8, 8, 2), 256>>>();          // T1 = P*P ; T2 = P*SigN
        k_mm<<<dim3(8, 8), 256>>>(P, T1, T2, 1);  // P = 1.5P - 0.5*T1*T2
    }
    k_mm<<<dim3(8, 8), 256>>>(M, rot, P, 2);      // M = s*rot*P (+ bf16 split)
    k_bias<<<1, 256>>>();
    k_out_mma<<<dim3(8, 2, 64), 256, OUT_SMEM>>>(out);
}